// round 14
// baseline (speedup 1.0000x reference)
#include <cuda_runtime.h>

#define BATCH 8
#define CH 128
#define HH 128
#define WW 128
#define KW 9
#define HWC (HH * WW * CH)
#define NCTA 128
#define NTHR 128
#define CLSZ 16
#define AROW 130            // u64 row stride in SMEM (padded: conflict-free)
#define SMEM_BYTES (2 * 72 * AROW * 8)   // w_s + a_s = 149760 B

// fp32 working state in (b, i, j, c) layout. 64 MB static device scratch.
__device__ float g_y[BATCH * HH * WW * CH];
// Barrier state for the FALLBACK path only (cluster path never touches it).
// Protocol restores all of it to 0 before kernel exit (graph-replay safe).
__device__ int g_bars[128];
__device__ int g_done;

typedef unsigned long long u64;

__device__ __forceinline__ u64 pack2(float x) {
    u64 r;
    asm("mov.b64 %0, {%1, %1};" : "=l"(r) : "f"(x));
    return r;
}
__device__ __forceinline__ u64 packf2(float x, float y) {
    u64 r;
    asm("mov.b64 %0, {%1, %2};" : "=l"(r) : "f"(x), "f"(y));
    return r;
}
__device__ __forceinline__ void fma2(u64& d, u64 a, u64 b) {
    asm("fma.rn.f32x2 %0, %1, %2, %0;" : "+l"(d) : "l"(a), "l"(b));
}
__device__ __forceinline__ float2 unpack2(u64 v) {
    float2 f;
    asm("mov.b64 {%0, %1}, %2;" : "=f"(f.x), "=f"(f.y) : "l"(v));
    return f;
}

// ---------------------------------------------------------------------------
// Transpose in: x (B,C,H,W) -> g_y (B,H,W,C)
// ---------------------------------------------------------------------------
__global__ void t_in_kernel(const float* __restrict__ x) {
    __shared__ float tile[32][33];
    int b = blockIdx.z >> 7;
    int h = blockIdx.z & 127;
    int w0 = blockIdx.x * 32;
    int c0 = blockIdx.y * 32;
    int tx = threadIdx.x, ty = threadIdx.y;
#pragma unroll
    for (int k = 0; k < 32; k += 8) {
        int c = c0 + ty + k;
        tile[ty + k][tx] = x[(((b * CH + c) * HH + h) * WW) + w0 + tx];
    }
    __syncthreads();
#pragma unroll
    for (int k = 0; k < 32; k += 8) {
        int w = w0 + ty + k;
        g_y[(((b * HH + h) * WW + w) * CH) + c0 + tx] = tile[tx][ty + k];
    }
}

// ---------------------------------------------------------------------------
// Transpose out: g_y (B,H,W,C) -> out (B,C,H,W)
// ---------------------------------------------------------------------------
__global__ void t_out_kernel(float* __restrict__ o) {
    __shared__ float tile[32][33];
    int b = blockIdx.z >> 7;
    int h = blockIdx.z & 127;
    int w0 = blockIdx.x * 32;
    int c0 = blockIdx.y * 32;
    int tx = threadIdx.x, ty = threadIdx.y;
#pragma unroll
    for (int k = 0; k < 32; k += 8) {
        int w = w0 + ty + k;
        tile[ty + k][tx] = g_y[(((b * HH + h) * WW + w) * CH) + c0 + tx];
    }
    __syncthreads();
#pragma unroll
    for (int k = 0; k < 32; k += 8) {
        int c = c0 + ty + k;
        o[(((b * CH + c) * HH + h) * WW) + w0 + tx] = tile[tx][ty + k];
    }
}

// ---------------------------------------------------------------------------
// Shared per-step body. CTA (cox, mh) within a batch: co tile 16 ch,
// m half 64 positions. Weights resident in SMEM as f32x2 co-pairs:
// w_s[(t*8+cop)*AROW + ci]. Prev line staged duplicated: a_s[r*AROW+ci]=(v,v).
// 128 threads; warp layout: cop = (lane&3)|((warp&2)<<1) (4 per warp),
// mg = (lane>>2)|((warp&1)<<3) (8 per warp -> full 128B act wavefronts).
// Thread tile: 4 m (mg + {0,16,32,48}) x 2 co (one f32x2 pair).
// Hot loop per ci-pair: 5x LDS.128 + 8x FFMA2.
// ---------------------------------------------------------------------------
__device__ __forceinline__ void stage_weights(u64* w_s, const float* __restrict__ Kw,
                                              int co0, int tid) {
    for (int idx = tid; idx < KW * 8 * CH; idx += NTHR) {
        int t = idx >> 10;
        int rem = idx & 1023;
        int cp = rem >> 7;
        int ci = rem & 127;
        float2 wv = *(const float2*)(Kw + (size_t)(t * CH + ci) * CH + co0 + 2 * cp);
        w_s[(t * 8 + cp) * AROW + ci] = packf2(wv.x, wv.y);
    }
}

__device__ __forceinline__ void step_body(
    u64* w_s, u64* a_s, float* ybase, int cur, int prev,
    int stride_p, int stride_m, int mstart, int co0,
    int tid, int cop, int mg) {
    // Prefetch RMW olds (cur line is stable until this step writes it).
    float* cb = ybase + (size_t)cur * stride_p;
    const int co = co0 + cop * 2;
    float2 old0 = *(float2*)(cb + (size_t)(mstart + mg) * stride_m + co);
    float2 old1 = *(float2*)(cb + (size_t)(mstart + mg + 16) * stride_m + co);
    float2 old2 = *(float2*)(cb + (size_t)(mstart + mg + 32) * stride_m + co);
    float2 old3 = *(float2*)(cb + (size_t)(mstart + mg + 48) * stride_m + co);

    // Stage prev line (72 conv-positions incl. halo, duplicated f32x2).
    const float* pb = ybase + (size_t)prev * stride_p;
    for (int j = tid; j < 72 * 32; j += NTHR) {
        int r = j >> 5;        // 0..71
        int c4 = j & 31;       // float4 chunk; ci = 4*c4
        int pos = mstart - 4 + r;
        float4 v = make_float4(0.f, 0.f, 0.f, 0.f);
        if (pos >= 0 && pos < 128)
            v = *(const float4*)(pb + (size_t)pos * stride_m + 4 * c4);
        ulonglong2* dst = (ulonglong2*)(a_s + r * AROW + 4 * c4);
        ulonglong2 d0, d1;
        d0.x = pack2(v.x); d0.y = pack2(v.y);
        d1.x = pack2(v.z); d1.y = pack2(v.w);
        dst[0] = d0;
        dst[1] = d1;
    }
    __syncthreads();

    u64 acc0 = 0, acc1 = 0, acc2 = 0, acc3 = 0;
    for (int t = 0; t < KW; ++t) {
        const u64* wr = w_s + (t * 8 + cop) * AROW;
        const u64* ar = a_s + (mg + t) * AROW;
#pragma unroll 8
        for (int ci = 0; ci < CH; ci += 2) {
            ulonglong2 wv = *(const ulonglong2*)(wr + ci);
            ulonglong2 v0 = *(const ulonglong2*)(ar + ci);
            ulonglong2 v1 = *(const ulonglong2*)(ar + 16 * AROW + ci);
            ulonglong2 v2 = *(const ulonglong2*)(ar + 32 * AROW + ci);
            ulonglong2 v3 = *(const ulonglong2*)(ar + 48 * AROW + ci);
            fma2(acc0, v0.x, wv.x);
            fma2(acc1, v1.x, wv.x);
            fma2(acc2, v2.x, wv.x);
            fma2(acc3, v3.x, wv.x);
            fma2(acc0, v0.y, wv.y);
            fma2(acc1, v1.y, wv.y);
            fma2(acc2, v2.y, wv.y);
            fma2(acc3, v3.y, wv.y);
        }
    }

    // Writeback: cur line += relu(acc)
    float2 rr;
    rr = unpack2(acc0);
    old0.x += fmaxf(rr.x, 0.f); old0.y += fmaxf(rr.y, 0.f);
    *(float2*)(cb + (size_t)(mstart + mg) * stride_m + co) = old0;
    rr = unpack2(acc1);
    old1.x += fmaxf(rr.x, 0.f); old1.y += fmaxf(rr.y, 0.f);
    *(float2*)(cb + (size_t)(mstart + mg + 16) * stride_m + co) = old1;
    rr = unpack2(acc2);
    old2.x += fmaxf(rr.x, 0.f); old2.y += fmaxf(rr.y, 0.f);
    *(float2*)(cb + (size_t)(mstart + mg + 32) * stride_m + co) = old2;
    rr = unpack2(acc3);
    old3.x += fmaxf(rr.x, 0.f); old3.y += fmaxf(rr.y, 0.f);
    *(float2*)(cb + (size_t)(mstart + mg + 48) * stride_m + co) = old3;
}

// ---------------------------------------------------------------------------
// Cluster variant: one 16-CTA cluster per batch; HW cluster barrier per step.
// barrier.cluster.arrive (release) / wait (acquire) gives cluster-wide
// visibility of the RMW global stores; the sync also invalidates L1D so the
// next step's staging loads observe peer writes.
// ---------------------------------------------------------------------------
__global__ void __launch_bounds__(NTHR, 1) scan_cluster_kernel(
    const float* __restrict__ Kw, int first, int dir, int stride_p, int stride_m) {
    extern __shared__ u64 sm[];
    u64* w_s = sm;                 // 72*AROW u64
    u64* a_s = sm + 72 * AROW;     // 72*AROW u64

    const int tid = threadIdx.x;
    const int bx = blockIdx.x;
    const int inner = bx & 15;     // rank within cluster (= within batch)
    const int b = bx >> 4;
    const int co0 = (inner & 7) * 16;
    const int mstart = (inner >> 3) * 64;
    const int w = tid >> 5, lane = tid & 31;
    const int cop = (lane & 3) | ((w & 2) << 1);   // 0..7
    const int mg = (lane >> 2) | ((w & 1) << 3);   // 0..15

    stage_weights(w_s, Kw, co0, tid);
    __syncthreads();

    float* ybase = g_y + (size_t)b * HWC;

    for (int s = 0; s < 127; ++s) {
        int cur = first + dir * s;
        step_body(w_s, a_s, ybase, cur, cur - dir, stride_p, stride_m,
                  mstart, co0, tid, cop, mg);
        if (s < 126) {
            asm volatile("barrier.cluster.arrive.aligned;" ::: "memory");
            asm volatile("barrier.cluster.wait.aligned;" ::: "memory");
        }
    }
}

// ---------------------------------------------------------------------------
// Fallback variant: software global barrier across all 128 CTAs (R10 scheme).
// ---------------------------------------------------------------------------
__global__ void __launch_bounds__(NTHR, 1) scan_global_kernel(
    const float* __restrict__ Kw, int first, int dir, int stride_p, int stride_m) {
    extern __shared__ u64 sm[];
    u64* w_s = sm;
    u64* a_s = sm + 72 * AROW;

    const int tid = threadIdx.x;
    const int bx = blockIdx.x;
    const int inner = bx & 15;
    const int b = bx >> 4;
    const int co0 = (inner & 7) * 16;
    const int mstart = (inner >> 3) * 64;
    const int w = tid >> 5, lane = tid & 31;
    const int cop = (lane & 3) | ((w & 2) << 1);
    const int mg = (lane >> 2) | ((w & 1) << 3);

    stage_weights(w_s, Kw, co0, tid);
    __syncthreads();

    float* ybase = g_y + (size_t)b * HWC;

    for (int s = 0; s < 127; ++s) {
        int cur = first + dir * s;
        step_body(w_s, a_s, ybase, cur, cur - dir, stride_p, stride_m,
                  mstart, co0, tid, cop, mg);
        if (s < 126) {
            __threadfence();
            __syncthreads();
            if (tid == 0) {
                atomicAdd(&g_bars[s], 1);
                while (*(volatile int*)&g_bars[s] < NCTA) { }
                __threadfence();
            }
            __syncthreads();
            if (bx == 0 && tid == 0 && s > 0) g_bars[s - 1] = 0;
        }
    }

    // End protocol: restore barrier state to zeros for the next launch/replay.
    __threadfence();
    __syncthreads();
    if (tid == 0) {
        atomicAdd(&g_done, 1);
        if (bx == 0) {
            while (*(volatile int*)&g_done < NCTA) { }
            g_bars[125] = 0;
            __threadfence();
            g_done = 0;
            __threadfence();
        }
    }
}

// ---------------------------------------------------------------------------
extern "C" void kernel_launch(void* const* d_in, const int* in_sizes, int n_in,
                              void* d_out, int out_size) {
    const float* x   = (const float*)d_in[0];
    const float* ktd = (const float*)d_in[1];
    const float* kdt = (const float*)d_in[2];
    const float* klr = (const float*)d_in[3];
    const float* krl = (const float*)d_in[4];

    cudaFuncSetAttribute(scan_cluster_kernel,
                         cudaFuncAttributeMaxDynamicSharedMemorySize, SMEM_BYTES);
    cudaFuncSetAttribute(scan_global_kernel,
                         cudaFuncAttributeMaxDynamicSharedMemorySize, SMEM_BYTES);

    // Decide (at capture time) whether a 16-CTA cluster launch is possible.
    bool use_cluster = false;
    {
        cudaError_t e = cudaFuncSetAttribute(
            scan_cluster_kernel, cudaFuncAttributeNonPortableClusterSizeAllowed, 1);
        if (e == cudaSuccess) {
            cudaLaunchConfig_t qcfg = {};
            qcfg.gridDim = dim3(NCTA, 1, 1);
            qcfg.blockDim = dim3(NTHR, 1, 1);
            qcfg.dynamicSmemBytes = SMEM_BYTES;
            int maxC = 0;
            if (cudaOccupancyMaxPotentialClusterSize(&maxC, (void*)scan_cluster_kernel,
                                                     &qcfg) == cudaSuccess &&
                maxC >= CLSZ)
                use_cluster = true;
        }
        cudaGetLastError();  // clear any sticky non-fatal error from the probe
    }

    dim3 tb(32, 8);
    dim3 tg(WW / 32, CH / 32, BATCH * HH);
    t_in_kernel<<<tg, tb>>>(x);

    const int ROW = WW * CH;  // 16384
    const float* Ks[4]    = {ktd, kdt, klr, krl};
    const int firsts[4]   = {1, HH - 2, 1, WW - 2};
    const int dirs[4]     = {1, -1, 1, -1};
    const int strides_p[4] = {ROW, ROW, CH, CH};
    const int strides_m[4] = {CH, CH, ROW, ROW};

    for (int d = 0; d < 4; ++d) {
        if (use_cluster) {
            cudaLaunchConfig_t cfg = {};
            cfg.gridDim = dim3(NCTA, 1, 1);
            cfg.blockDim = dim3(NTHR, 1, 1);
            cfg.dynamicSmemBytes = SMEM_BYTES;
            cfg.stream = 0;
            cudaLaunchAttribute at[1];
            at[0].id = cudaLaunchAttributeClusterDimension;
            at[0].val.clusterDim.x = CLSZ;
            at[0].val.clusterDim.y = 1;
            at[0].val.clusterDim.z = 1;
            cfg.attrs = at;
            cfg.numAttrs = 1;
            cudaLaunchKernelEx(&cfg, scan_cluster_kernel,
                               Ks[d], firsts[d], dirs[d], strides_p[d], strides_m[d]);
        } else {
            scan_global_kernel<<<NCTA, NTHR, SMEM_BYTES>>>(
                Ks[d], firsts[d], dirs[d], strides_p[d], strides_m[d]);
        }
    }

    t_out_kernel<<<tg, tb>>>((float*)d_out);
}

// round 15
// speedup vs baseline: 1.9244x; 1.9244x over previous
#include <cuda_runtime.h>

#define BATCH 8
#define CH 128
#define HH 128
#define WW 128
#define KW 9
#define HWC (HH * WW * CH)
#define NCTA 128
#define NTHR 256
#define AROW 130            // u64 row stride in SMEM (padded: conflict-free)
#define SMEM_BYTES (2 * 72 * AROW * 8)   // w_s + a_s = 149760 B

// fp32 working state in (b, i, j, c) layout. 64 MB static device scratch.
__device__ float g_y[BATCH * HH * WW * CH];
// Global-barrier state; protocol restores all of it to 0 before kernel exit,
// so every launch (and every graph replay) starts from zeros.
__device__ int g_bars[128];
__device__ int g_done;

typedef unsigned long long u64;

__device__ __forceinline__ u64 pack2(float x) {
    u64 r;
    asm("mov.b64 %0, {%1, %1};" : "=l"(r) : "f"(x));
    return r;
}
__device__ __forceinline__ u64 packf2(float x, float y) {
    u64 r;
    asm("mov.b64 %0, {%1, %2};" : "=l"(r) : "f"(x), "f"(y));
    return r;
}
__device__ __forceinline__ void fma2(u64& d, u64 a, u64 b) {
    asm("fma.rn.f32x2 %0, %1, %2, %0;" : "+l"(d) : "l"(a), "l"(b));
}
__device__ __forceinline__ void add2(u64& d, u64 a) {
    asm("add.rn.f32x2 %0, %0, %1;" : "+l"(d) : "l"(a));
}
__device__ __forceinline__ float2 unpack2(u64 v) {
    float2 f;
    asm("mov.b64 {%0, %1}, %2;" : "=f"(f.x), "=f"(f.y) : "l"(v));
    return f;
}

// ---------------------------------------------------------------------------
// Transpose in: x (B,C,H,W) -> g_y (B,H,W,C)
// ---------------------------------------------------------------------------
__global__ void t_in_kernel(const float* __restrict__ x) {
    __shared__ float tile[32][33];
    int b = blockIdx.z >> 7;
    int h = blockIdx.z & 127;
    int w0 = blockIdx.x * 32;
    int c0 = blockIdx.y * 32;
    int tx = threadIdx.x, ty = threadIdx.y;
#pragma unroll
    for (int k = 0; k < 32; k += 8) {
        int c = c0 + ty + k;
        tile[ty + k][tx] = x[(((b * CH + c) * HH + h) * WW) + w0 + tx];
    }
    __syncthreads();
#pragma unroll
    for (int k = 0; k < 32; k += 8) {
        int w = w0 + ty + k;
        g_y[(((b * HH + h) * WW + w) * CH) + c0 + tx] = tile[tx][ty + k];
    }
}

// ---------------------------------------------------------------------------
// Transpose out: g_y (B,H,W,C) -> out (B,C,H,W)
// ---------------------------------------------------------------------------
__global__ void t_out_kernel(float* __restrict__ o) {
    __shared__ float tile[32][33];
    int b = blockIdx.z >> 7;
    int h = blockIdx.z & 127;
    int w0 = blockIdx.x * 32;
    int c0 = blockIdx.y * 32;
    int tx = threadIdx.x, ty = threadIdx.y;
#pragma unroll
    for (int k = 0; k < 32; k += 8) {
        int w = w0 + ty + k;
        tile[ty + k][tx] = g_y[(((b * HH + h) * WW + w) * CH) + c0 + tx];
    }
    __syncthreads();
#pragma unroll
    for (int k = 0; k < 32; k += 8) {
        int c = c0 + ty + k;
        o[(((b * CH + c) * HH + h) * WW) + w0 + tx] = tile[tx][ty + k];
    }
}

// ---------------------------------------------------------------------------
// Persistent per-direction scan kernel, 127 steps, global 128-CTA barrier.
// CTA (cox, b, mh): co tile 16 ch, batch b, m half 64 positions.
// Weights resident in SMEM as f32x2 co-pairs: w_s[(t*8+cop)*AROW + ci].
// Prev line staged per step duplicated: a_s[r*AROW + ci] = (v,v).
//
// SPLIT-K over 256 threads: kh = tid>>7 selects ci half [kh*64, kh*64+64).
// Within each half, thread (cop = tid&7, mg = (tid>>3)&15) computes the
// SAME 4m x 2co tile as the proven R10-best kernel (m = mstart+mg+{0,16,32,48},
// co pair co0+2*cop) — per-warp wavefront pattern is unchanged, iterations
// per warp halve, 2 warps/SMSP hide LDS + L2 latency.
// Halves are combined via an SMEM reduction (a_s reused as scratch), then
// kh=0 threads do the RMW writeback (olds prefetched at step start).
// ---------------------------------------------------------------------------
__global__ void __launch_bounds__(NTHR, 1) scan_kernel(
    const float* __restrict__ Kw, int first, int dir, int stride_p, int stride_m) {
    extern __shared__ u64 sm[];
    u64* w_s = sm;                 // 72*AROW u64
    u64* a_s = sm + 72 * AROW;     // 72*AROW u64 (also reduction scratch)

    const int tid = threadIdx.x;
    const int bx = blockIdx.x;
    const int cox = bx & 7;
    const int b = (bx >> 3) & 7;
    const int mh = bx >> 6;
    const int co0 = cox * 16;
    const int mstart = mh * 64;
    const int low = tid & 127;
    const int kh = tid >> 7;            // ci half: 0 or 1
    const int ci0 = kh << 6;            // 0 or 64
    const int cop = low & 7;            // co pair 0..7
    const int mg = low >> 3;            // 0..15

    // Stage weights once per direction: pack co pairs into u64.
    for (int idx = tid; idx < KW * 8 * CH; idx += NTHR) {
        int t = idx >> 10;
        int rem = idx & 1023;
        int cp = rem >> 7;
        int ci = rem & 127;
        float2 wv = *(const float2*)(Kw + (size_t)(t * CH + ci) * CH + co0 + 2 * cp);
        w_s[(t * 8 + cp) * AROW + ci] = packf2(wv.x, wv.y);
    }
    __syncthreads();

    float* ybase = g_y + (size_t)b * HWC;
    const int co = co0 + cop * 2;

    for (int s = 0; s < 127; ++s) {
        int cur = first + dir * s;
        int prev = cur - dir;
        float* cb = ybase + (size_t)cur * stride_p;

        // Prefetch RMW olds early (own-slice data: only this CTA writes it,
        // and only at this step). kh=0 threads own the writeback.
        float2 old0, old1, old2, old3;
        if (kh == 0) {
            old0 = *(float2*)(cb + (size_t)(mstart + mg) * stride_m + co);
            old1 = *(float2*)(cb + (size_t)(mstart + mg + 16) * stride_m + co);
            old2 = *(float2*)(cb + (size_t)(mstart + mg + 32) * stride_m + co);
            old3 = *(float2*)(cb + (size_t)(mstart + mg + 48) * stride_m + co);
        }

        // Stage prev line (72 conv-positions incl. halo, duplicated f32x2).
        const float* pb = ybase + (size_t)prev * stride_p;
        for (int j = tid; j < 72 * 32; j += NTHR) {
            int r = j >> 5;        // 0..71
            int c4 = j & 31;       // float4 chunk; ci = 4*c4
            int pos = mstart - 4 + r;
            float4 v = make_float4(0.f, 0.f, 0.f, 0.f);
            if (pos >= 0 && pos < 128)
                v = *(const float4*)(pb + (size_t)pos * stride_m + 4 * c4);
            ulonglong2* dst = (ulonglong2*)(a_s + r * AROW + 4 * c4);
            ulonglong2 d0, d1;
            d0.x = pack2(v.x); d0.y = pack2(v.y);
            d1.x = pack2(v.z); d1.y = pack2(v.w);
            dst[0] = d0;
            dst[1] = d1;
        }
        __syncthreads();

        u64 acc0 = 0, acc1 = 0, acc2 = 0, acc3 = 0;
        for (int t = 0; t < KW; ++t) {
            const u64* wr = w_s + (t * 8 + cop) * AROW + ci0;
            const u64* ar = a_s + (mg + t) * AROW + ci0;
#pragma unroll 8
            for (int ci = 0; ci < 64; ci += 2) {
                ulonglong2 wv = *(const ulonglong2*)(wr + ci);
                ulonglong2 v0 = *(const ulonglong2*)(ar + ci);
                ulonglong2 v1 = *(const ulonglong2*)(ar + 16 * AROW + ci);
                ulonglong2 v2 = *(const ulonglong2*)(ar + 32 * AROW + ci);
                ulonglong2 v3 = *(const ulonglong2*)(ar + 48 * AROW + ci);
                fma2(acc0, v0.x, wv.x);
                fma2(acc1, v1.x, wv.x);
                fma2(acc2, v2.x, wv.x);
                fma2(acc3, v3.x, wv.x);
                fma2(acc0, v0.y, wv.y);
                fma2(acc1, v1.y, wv.y);
                fma2(acc2, v2.y, wv.y);
                fma2(acc3, v3.y, wv.y);
            }
        }

        // Combine K-halves: kh=1 parks its accs in SMEM (a_s reused; all
        // mainloop reads are done after the sync), kh=0 adds and writes back.
        __syncthreads();
        if (kh == 1) {
            a_s[low]       = acc0;
            a_s[low + 128] = acc1;
            a_s[low + 256] = acc2;
            a_s[low + 384] = acc3;
        }
        __syncthreads();
        if (kh == 0) {
            add2(acc0, a_s[low]);
            add2(acc1, a_s[low + 128]);
            add2(acc2, a_s[low + 256]);
            add2(acc3, a_s[low + 384]);
            float2 rr;
            rr = unpack2(acc0);
            old0.x += fmaxf(rr.x, 0.f); old0.y += fmaxf(rr.y, 0.f);
            *(float2*)(cb + (size_t)(mstart + mg) * stride_m + co) = old0;
            rr = unpack2(acc1);
            old1.x += fmaxf(rr.x, 0.f); old1.y += fmaxf(rr.y, 0.f);
            *(float2*)(cb + (size_t)(mstart + mg + 16) * stride_m + co) = old1;
            rr = unpack2(acc2);
            old2.x += fmaxf(rr.x, 0.f); old2.y += fmaxf(rr.y, 0.f);
            *(float2*)(cb + (size_t)(mstart + mg + 32) * stride_m + co) = old2;
            rr = unpack2(acc3);
            old3.x += fmaxf(rr.x, 0.f); old3.y += fmaxf(rr.y, 0.f);
            *(float2*)(cb + (size_t)(mstart + mg + 48) * stride_m + co) = old3;
        }

        // Global barrier across all 128 CTAs (proven R10 scheme).
        // Slot s-1 is zeroed by CTA0 after slot s completes (provably dead).
        if (s < 126) {
            __threadfence();
            __syncthreads();
            if (tid == 0) {
                atomicAdd(&g_bars[s], 1);
                while (*(volatile int*)&g_bars[s] < NCTA) { }
                __threadfence();
            }
            __syncthreads();
            if (bx == 0 && tid == 0 && s > 0) g_bars[s - 1] = 0;
        }
    }

    // End protocol: restore barrier state to zeros for next launch / replay.
    __threadfence();
    __syncthreads();
    if (tid == 0) {
        atomicAdd(&g_done, 1);
        if (bx == 0) {
            while (*(volatile int*)&g_done < NCTA) { }
            g_bars[125] = 0;
            __threadfence();
            g_done = 0;
            __threadfence();
        }
    }
}

// ---------------------------------------------------------------------------
extern "C" void kernel_launch(void* const* d_in, const int* in_sizes, int n_in,
                              void* d_out, int out_size) {
    const float* x   = (const float*)d_in[0];
    const float* ktd = (const float*)d_in[1];
    const float* kdt = (const float*)d_in[2];
    const float* klr = (const float*)d_in[3];
    const float* krl = (const float*)d_in[4];

    cudaFuncSetAttribute(scan_kernel, cudaFuncAttributeMaxDynamicSharedMemorySize,
                         SMEM_BYTES);

    dim3 tb(32, 8);
    dim3 tg(WW / 32, CH / 32, BATCH * HH);
    t_in_kernel<<<tg, tb>>>(x);

    const int ROW = WW * CH;  // 16384
    // Top-down: scan i (stride_p=ROW), conv along j (stride_m=CH)
    scan_kernel<<<NCTA, NTHR, SMEM_BYTES>>>(ktd, 1, 1, ROW, CH);
    // Bottom-up
    scan_kernel<<<NCTA, NTHR, SMEM_BYTES>>>(kdt, HH - 2, -1, ROW, CH);
    // Left-right: scan j (stride_p=CH), conv along i (stride_m=ROW)
    scan_kernel<<<NCTA, NTHR, SMEM_BYTES>>>(klr, 1, 1, CH, ROW);
    // Right-left
    scan_kernel<<<NCTA, NTHR, SMEM_BYTES>>>(krl, WW - 2, -1, CH, ROW);

    t_out_kernel<<<tg, tb>>>((float*)d_out);
}